// round 11
// baseline (speedup 1.0000x reference)
#include <cuda_runtime.h>

// HarmonicOscillator — confirmed numerics (rel_err 2.6e-7):
//   v = f0_up * fl32(1/22050); interp = two muls + add (no contraction);
//   cumsum = XLA ReduceWindowRewriter(base=16), serial 16-folds per tile,
//   levels 262144->16384->1024->64->4 (terminal serial), combine
//   out = fl(outer_excl + inner), row 0 exact.
// R11: k1 tail-free (512 thr, P0+T1 only, 1.73 waves); k2 absorbs P1/T2 fold.

#define BATCH 8
#define FRAMES 512
#define NH 64
#define NS 262144              // 512*512
#define ROWS 16384             // NS/16

__device__ float g_P0[BATCH][NS];
__device__ float g_T1[BATCH][ROWS];   // raw tile sums (level-1 input)
__device__ float g_P1[BATCH][ROWS];   // level-1 within-tile prefixes
__device__ float g_S2[BATCH][1024];   // full scan of level-2 (scan2)

typedef unsigned long long u64;

__device__ __forceinline__ u64 pk(float lo, float hi) {
    u64 r; asm("mov.b64 %0,{%1,%2};" : "=l"(r) : "f"(lo), "f"(hi)); return r;
}
__device__ __forceinline__ void upk(u64 v, float& lo, float& hi) {
    asm("mov.b64 {%0,%1},%2;" : "=f"(lo), "=f"(hi) : "l"(v));
}
__device__ __forceinline__ u64 fma2(u64 a, u64 b, u64 c) {
    u64 d; asm("fma.rn.f32x2 %0,%1,%2,%3;" : "=l"(d) : "l"(a), "l"(b), "l"(c)); return d;
}
__device__ __forceinline__ u64 mul2(u64 a, u64 b) {
    u64 d; asm("mul.rn.f32x2 %0,%1,%2;" : "=l"(d) : "l"(a), "l"(b)); return d;
}
__device__ __forceinline__ u64 sub2(u64 a, u64 b) {
    u64 d; asm("sub.rn.f32x2 %0,%1,%2;" : "=l"(d) : "l"(a), "l"(b)); return d;
}

__device__ __forceinline__ float interp_c() {
    return (float)(511.0 / 262143.0);
}

__device__ __forceinline__ float compute_v(const float* __restrict__ sf0, int n) {
    float nf  = (float)n;
    float pos = __fmul_rn(nf, interp_c());
    float fi0 = floorf(pos);
    int   i0  = (int)fi0;
    int   i1  = min(i0 + 1, FRAMES - 1);
    float w   = __fadd_rn(pos, -fi0);
    float omw = __fadd_rn(1.0f, -w);
    float up  = __fadd_rn(__fmul_rn(sf0[i0], omw), __fmul_rn(sf0[i1], w));
    const float RECIP_SR = (float)(1.0 / 22050.0);
    return __fmul_rn(up, RECIP_SR);
}

// ---- k1: P0 tile prefixes + T1 tile sums (no tail) ----
__global__ void __launch_bounds__(512) k1(const float* __restrict__ f0) {
    const int b = blockIdx.y;
    const int t = threadIdx.x;                  // 0..511
    const int row = blockIdx.x * 512 + t;

    __shared__ float sf0[FRAMES];
    sf0[t] = f0[b * FRAMES + t];
    __syncthreads();

    const int base = row * 16;
    float x[16];
    float acc = 0.0f;
    #pragma unroll
    for (int c = 0; c < 16; ++c) {
        acc = __fadd_rn(acc, compute_v(sf0, base + c));
        x[c] = acc;
    }
    float4* dst = (float4*)(g_P0[b] + base);
    dst[0] = make_float4(x[0],  x[1],  x[2],  x[3]);
    dst[1] = make_float4(x[4],  x[5],  x[6],  x[7]);
    dst[2] = make_float4(x[8],  x[9],  x[10], x[11]);
    dst[3] = make_float4(x[12], x[13], x[14], x[15]);
    g_T1[b][row] = acc;
}

// ---- k2: P1/T2 fold + levels 2..4, emit scan2 ----
__global__ void __launch_bounds__(1024) k2() {
    const int b = blockIdx.x;
    const int t = threadIdx.x;                  // 0..1023
    __shared__ float sT2[1024];
    __shared__ float sP2[1024];
    __shared__ float sS3[64];
    __shared__ float sP4[4];

    {   // level-1: fold 16 T1 -> P1 prefixes + T2 sum (same order as before)
        float y[16];
        float a = 0.0f;
        #pragma unroll
        for (int c = 0; c < 16; ++c) {
            a = __fadd_rn(a, g_T1[b][t * 16 + c]);
            y[c] = a;
        }
        float4* dst = (float4*)(g_P1[b] + t * 16);
        dst[0] = make_float4(y[0],  y[1],  y[2],  y[3]);
        dst[1] = make_float4(y[4],  y[5],  y[6],  y[7]);
        dst[2] = make_float4(y[8],  y[9],  y[10], y[11]);
        dst[3] = make_float4(y[12], y[13], y[14], y[15]);
        sT2[t] = a;
    }
    __syncthreads();

    if (t < 64) {                               // P2: 64 serial folds of 16
        float a = 0.0f;
        #pragma unroll
        for (int c = 0; c < 16; ++c) {
            a = __fadd_rn(a, sT2[t * 16 + c]);
            sP2[t * 16 + c] = a;
        }
    }
    __syncthreads();
    if (t < 4) {                                // P3 over T3
        float a = 0.0f;
        #pragma unroll
        for (int c = 0; c < 16; ++c) {
            a = __fadd_rn(a, sP2[(t * 16 + c) * 16 + 15]);
            sS3[t * 16 + c] = a;
        }
    }
    __syncthreads();
    if (t == 0) {                               // P4 (terminal serial)
        float a = 0.0f;
        #pragma unroll
        for (int c = 0; c < 4; ++c) {
            a = __fadd_rn(a, sS3[c * 16 + 15]);
            sP4[c] = a;
        }
    }
    __syncthreads();
    if (t < 48) {                               // scan3 in place (m >= 16)
        int m = t + 16;
        sS3[m] = __fadd_rn(sP4[(m >> 4) - 1], sS3[m]);
    }
    __syncthreads();
    if (t < 1024) {                             // scan2 -> g_S2
        float p2 = sP2[t];
        g_S2[b][t] = (t < 16) ? p2 : __fadd_rn(sS3[(t >> 4) - 1], p2);
    }
}

// ---- S reconstruction (exact reference fl nesting) ----
__device__ __forceinline__ float recon_S(int b, int n) {
    float p0 = g_P0[b][n];
    const int r1i = n >> 4;
    if (r1i == 0) return p0;
    const int j = r1i - 1;
    float p1 = g_P1[b][j];
    const int r2 = j >> 4;
    float s1 = (r2 == 0) ? p1 : __fadd_rn(g_S2[b][r2 - 1], p1);
    return __fadd_rn(s1, p0);
}

// ---- k_main: packed f32x2 synthesis, 2 samples/thread ----
__global__ void __launch_bounds__(128) k_main(const float* __restrict__ amps,
                                              float* __restrict__ out) {
    const int b = blockIdx.y;
    const int n0 = blockIdx.x * 256;
    const int t = threadIdx.x;                   // 0..127
    const int nA = n0 + t;
    const int nB = n0 + t + 128;

    float posF = __fmul_rn((float)n0, interp_c());
    const int i0f = (int)floorf(posF);

    __shared__ u64 sA0[2][32];
    __shared__ u64 sDF[2][32];
    if (t < 64) {
        int g = t >> 5;
        int s = t & 31;
        int r0 = min(i0f + g, FRAMES - 1);
        int r1 = min(r0 + 1, FRAMES - 1);
        const u64* rowA = (const u64*)(amps + ((size_t)b * FRAMES + r0) * NH);
        const u64* rowB = (const u64*)(amps + ((size_t)b * FRAMES + r1) * NH);
        u64 a0 = __ldg(rowA + s);
        u64 a1 = __ldg(rowB + s);
        sA0[g][s] = a0;
        sDF[g][s] = sub2(a1, a0);
    }

    const float TWO_PI_F = 6.283185307179586f;
    float phA = __fmul_rn(recon_S(b, nA), TWO_PI_F);
    float phB = __fmul_rn(recon_S(b, nB), TWO_PI_F);

    float posA = __fmul_rn((float)nA, interp_c());
    float fA   = floorf(posA);
    int   iA   = (int)fA;
    float wA   = __fadd_rn(posA, -fA);
    const int gA = iA - i0f;

    float posB = __fmul_rn((float)nB, interp_c());
    float fB   = floorf(posB);
    int   iB   = (int)fB;
    float wB   = __fadd_rn(posB, -fB);
    const int gB = iB - i0f;

    __syncthreads();

    const float INV2PI = (float)(1.0 / 6.283185307179586);
    const float C1 = 6.283185482025146484375f;
    const float C2 = -1.7484556e-7f;
    const float MAGIC = 12582912.0f;             // 1.5 * 2^23

    u64 wA2 = pk(wA, wA);
    u64 wB2 = pk(wB, wB);
    u64 pA2 = pk(phA, phA);
    u64 pB2 = pk(phB, phB);
    u64 IV2 = pk(INV2PI, INV2PI);
    u64 MG2 = pk(MAGIC, MAGIC);
    u64 C1n = pk(-C1, -C1);
    u64 C2n = pk(-C2, -C2);
    u64 accA0 = pk(0.0f, 0.0f), accA1 = pk(0.0f, 0.0f);
    u64 accB0 = pk(0.0f, 0.0f), accB1 = pk(0.0f, 0.0f);

    #pragma unroll
    for (int q = 0; q < NH / 4; ++q) {
        u64 h0 = pk((float)(4 * q + 1), (float)(4 * q + 2));
        u64 h1 = pk((float)(4 * q + 3), (float)(4 * q + 4));

        u64 ampA0 = fma2(wA2, sDF[gA][2 * q],     sA0[gA][2 * q]);
        u64 ampA1 = fma2(wA2, sDF[gA][2 * q + 1], sA0[gA][2 * q + 1]);
        u64 ampB0 = fma2(wB2, sDF[gB][2 * q],     sA0[gB][2 * q]);
        u64 ampB1 = fma2(wB2, sDF[gB][2 * q + 1], sA0[gB][2 * q + 1]);

        {   u64 pr = mul2(pA2, h0);
            u64 tt = fma2(pr, IV2, MG2);
            u64 kf = sub2(tt, MG2);
            u64 r  = fma2(kf, C1n, pr);
            r      = fma2(kf, C2n, r);
            float rl, rh; upk(r, rl, rh);
            accA0  = fma2(pk(__sinf(rl), __sinf(rh)), ampA0, accA0);
        }
        {   u64 pr = mul2(pB2, h0);
            u64 tt = fma2(pr, IV2, MG2);
            u64 kf = sub2(tt, MG2);
            u64 r  = fma2(kf, C1n, pr);
            r      = fma2(kf, C2n, r);
            float rl, rh; upk(r, rl, rh);
            accB0  = fma2(pk(__sinf(rl), __sinf(rh)), ampB0, accB0);
        }
        {   u64 pr = mul2(pA2, h1);
            u64 tt = fma2(pr, IV2, MG2);
            u64 kf = sub2(tt, MG2);
            u64 r  = fma2(kf, C1n, pr);
            r      = fma2(kf, C2n, r);
            float rl, rh; upk(r, rl, rh);
            accA1  = fma2(pk(__sinf(rl), __sinf(rh)), ampA1, accA1);
        }
        {   u64 pr = mul2(pB2, h1);
            u64 tt = fma2(pr, IV2, MG2);
            u64 kf = sub2(tt, MG2);
            u64 r  = fma2(kf, C1n, pr);
            r      = fma2(kf, C2n, r);
            float rl, rh; upk(r, rl, rh);
            accB1  = fma2(pk(__sinf(rl), __sinf(rh)), ampB1, accB1);
        }
    }
    float a0l, a0h, a1l, a1h, b0l, b0h, b1l, b1h;
    upk(accA0, a0l, a0h); upk(accA1, a1l, a1h);
    upk(accB0, b0l, b0h); upk(accB1, b1l, b1h);
    out[(size_t)b * NS + nA] = (a0l + a0h) + (a1l + a1h);
    out[(size_t)b * NS + nB] = (b0l + b0h) + (b1l + b1h);
}

extern "C" void kernel_launch(void* const* d_in, const int* in_sizes, int n_in,
                              void* d_out, int out_size) {
    const float* f0   = (const float*)d_in[0];   // (8, 512)
    const float* amps = (const float*)d_in[1];   // (8, 512, 64)
    float* out = (float*)d_out;                  // (8, 262144)

    k1<<<dim3(ROWS / 512, BATCH), 512>>>(f0);
    k2<<<BATCH, 1024>>>();
    k_main<<<dim3(NS / 256, BATCH), 128>>>(amps, out);
}

// round 12
// speedup vs baseline: 1.1176x; 1.1176x over previous
#include <cuda_runtime.h>

// HarmonicOscillator — confirmed numerics (rel_err 2.6e-7):
//   v = f0_up * fl32(1/22050); interp = two muls + add (no contraction);
//   cumsum = XLA ReduceWindowRewriter(base=16), serial 16-folds per tile,
//   levels 262144->16384->1024->64->4 (terminal serial), combine
//   out = fl(outer_excl + inner), row 0 exact.
// R12: revert to R10 partition (P1 fold in k1, tiny k2). k1 drops the smem
//      f0 staging: 3 direct __ldg per tile + per-sample select (i0 spans
//      at most {j, j+1} within one 16-sample tile). Bit-identical values.

#define BATCH 8
#define FRAMES 512
#define NH 64
#define NS 262144              // 512*512
#define ROWS 16384             // NS/16

__device__ float g_P0[BATCH][NS];
__device__ float g_P1[BATCH][ROWS];
__device__ float g_T2[BATCH][1024];
__device__ float g_S2[BATCH][1024];

typedef unsigned long long u64;

__device__ __forceinline__ u64 pk(float lo, float hi) {
    u64 r; asm("mov.b64 %0,{%1,%2};" : "=l"(r) : "f"(lo), "f"(hi)); return r;
}
__device__ __forceinline__ void upk(u64 v, float& lo, float& hi) {
    asm("mov.b64 {%0,%1},%2;" : "=f"(lo), "=f"(hi) : "l"(v));
}
__device__ __forceinline__ u64 fma2(u64 a, u64 b, u64 c) {
    u64 d; asm("fma.rn.f32x2 %0,%1,%2,%3;" : "=l"(d) : "l"(a), "l"(b), "l"(c)); return d;
}
__device__ __forceinline__ u64 mul2(u64 a, u64 b) {
    u64 d; asm("mul.rn.f32x2 %0,%1,%2;" : "=l"(d) : "l"(a), "l"(b)); return d;
}
__device__ __forceinline__ u64 sub2(u64 a, u64 b) {
    u64 d; asm("sub.rn.f32x2 %0,%1,%2;" : "=l"(d) : "l"(a), "l"(b)); return d;
}

__device__ __forceinline__ float interp_c() {
    return (float)(511.0 / 262143.0);
}

// ---- k1: P0 tile prefixes + P1 level-1 prefixes + T2 tile sums ----
__global__ void __launch_bounds__(256) k1(const float* __restrict__ f0) {
    const int b = blockIdx.y;
    const int t = threadIdx.x;                  // 0..255
    const int row = blockIdx.x * 256 + t;
    const float* fr = f0 + b * FRAMES;

    const int base = row * 16;

    // first-sample i0 for this tile; within tile i0 is j or j+1
    float posJ = __fmul_rn((float)base, interp_c());
    const int j = (int)floorf(posJ);
    const float v0 = __ldg(fr + j);
    const float v1 = __ldg(fr + min(j + 1, FRAMES - 1));
    const float v2 = __ldg(fr + min(j + 2, FRAMES - 1));

    float x[16];
    float acc = 0.0f;
    #pragma unroll
    for (int c = 0; c < 16; ++c) {
        const int n = base + c;
        float nf  = (float)n;
        float pos = __fmul_rn(nf, interp_c());
        float fi0 = floorf(pos);
        int   i0  = (int)fi0;
        int   i1  = min(i0 + 1, FRAMES - 1);
        float w   = __fadd_rn(pos, -fi0);
        float omw = __fadd_rn(1.0f, -w);
        float a = (i0 == j)     ? v0 : v1;
        float cc = (i1 == j + 1) ? v1 : v2;
        float up  = __fadd_rn(__fmul_rn(a, omw), __fmul_rn(cc, w));
        const float RECIP_SR = (float)(1.0 / 22050.0);
        float v   = __fmul_rn(up, RECIP_SR);
        acc = __fadd_rn(acc, v);
        x[c] = acc;
    }
    float4* dst = (float4*)(g_P0[b] + base);
    dst[0] = make_float4(x[0],  x[1],  x[2],  x[3]);
    dst[1] = make_float4(x[4],  x[5],  x[6],  x[7]);
    dst[2] = make_float4(x[8],  x[9],  x[10], x[11]);
    dst[3] = make_float4(x[12], x[13], x[14], x[15]);

    __shared__ float sT1[256];
    __shared__ float sP1[256];
    sT1[t] = acc;
    __syncthreads();
    if (t < 16) {
        float a2 = 0.0f;
        #pragma unroll
        for (int c = 0; c < 16; ++c) {
            a2 = __fadd_rn(a2, sT1[t * 16 + c]);
            sP1[t * 16 + c] = a2;
        }
        g_T2[b][blockIdx.x * 16 + t] = a2;
    }
    __syncthreads();
    g_P1[b][row] = sP1[t];
}

// ---- k2: levels 2..4, emit scan2 (1024/batch) ----
__global__ void k2() {
    const int b = blockIdx.x;
    const int t = threadIdx.x;                  // 0..127
    __shared__ float sP2[1024];
    __shared__ float sS3[64];
    __shared__ float sP4[4];

    if (t < 64) {
        float a = 0.0f;
        #pragma unroll
        for (int c = 0; c < 16; ++c) {
            a = __fadd_rn(a, g_T2[b][t * 16 + c]);
            sP2[t * 16 + c] = a;
        }
    }
    __syncthreads();
    if (t < 4) {
        float a = 0.0f;
        #pragma unroll
        for (int c = 0; c < 16; ++c) {
            a = __fadd_rn(a, sP2[(t * 16 + c) * 16 + 15]);
            sS3[t * 16 + c] = a;
        }
    }
    __syncthreads();
    if (t == 0) {
        float a = 0.0f;
        #pragma unroll
        for (int c = 0; c < 4; ++c) {
            a = __fadd_rn(a, sS3[c * 16 + 15]);
            sP4[c] = a;
        }
    }
    __syncthreads();
    if (t < 48) {
        int m = t + 16;
        sS3[m] = __fadd_rn(sP4[(m >> 4) - 1], sS3[m]);
    }
    __syncthreads();
    #pragma unroll
    for (int k = 0; k < 8; ++k) {
        int jj = t + k * 128;
        float p2 = sP2[jj];
        g_S2[b][jj] = (jj < 16) ? p2 : __fadd_rn(sS3[(jj >> 4) - 1], p2);
    }
}

// ---- S reconstruction (exact reference fl nesting) ----
__device__ __forceinline__ float recon_S(int b, int n) {
    float p0 = g_P0[b][n];
    const int r1i = n >> 4;
    if (r1i == 0) return p0;
    const int j = r1i - 1;
    float p1 = g_P1[b][j];
    const int r2 = j >> 4;
    float s1 = (r2 == 0) ? p1 : __fadd_rn(g_S2[b][r2 - 1], p1);
    return __fadd_rn(s1, p0);
}

// ---- k_main: packed f32x2 synthesis, 2 samples/thread ----
__global__ void __launch_bounds__(128) k_main(const float* __restrict__ amps,
                                              float* __restrict__ out) {
    const int b = blockIdx.y;
    const int n0 = blockIdx.x * 256;
    const int t = threadIdx.x;                   // 0..127
    const int nA = n0 + t;
    const int nB = n0 + t + 128;

    float posF = __fmul_rn((float)n0, interp_c());
    const int i0f = (int)floorf(posF);

    __shared__ u64 sA0[2][32];
    __shared__ u64 sDF[2][32];
    if (t < 64) {
        int g = t >> 5;
        int s = t & 31;
        int r0 = min(i0f + g, FRAMES - 1);
        int r1 = min(r0 + 1, FRAMES - 1);
        const u64* rowA = (const u64*)(amps + ((size_t)b * FRAMES + r0) * NH);
        const u64* rowB = (const u64*)(amps + ((size_t)b * FRAMES + r1) * NH);
        u64 a0 = __ldg(rowA + s);
        u64 a1 = __ldg(rowB + s);
        sA0[g][s] = a0;
        sDF[g][s] = sub2(a1, a0);
    }

    const float TWO_PI_F = 6.283185307179586f;
    float phA = __fmul_rn(recon_S(b, nA), TWO_PI_F);
    float phB = __fmul_rn(recon_S(b, nB), TWO_PI_F);

    float posA = __fmul_rn((float)nA, interp_c());
    float fA   = floorf(posA);
    int   iA   = (int)fA;
    float wA   = __fadd_rn(posA, -fA);
    const int gA = iA - i0f;

    float posB = __fmul_rn((float)nB, interp_c());
    float fB   = floorf(posB);
    int   iB   = (int)fB;
    float wB   = __fadd_rn(posB, -fB);
    const int gB = iB - i0f;

    __syncthreads();

    const float INV2PI = (float)(1.0 / 6.283185307179586);
    const float C1 = 6.283185482025146484375f;
    const float C2 = -1.7484556e-7f;
    const float MAGIC = 12582912.0f;             // 1.5 * 2^23

    u64 wA2 = pk(wA, wA);
    u64 wB2 = pk(wB, wB);
    u64 pA2 = pk(phA, phA);
    u64 pB2 = pk(phB, phB);
    u64 IV2 = pk(INV2PI, INV2PI);
    u64 MG2 = pk(MAGIC, MAGIC);
    u64 C1n = pk(-C1, -C1);
    u64 C2n = pk(-C2, -C2);
    u64 accA0 = pk(0.0f, 0.0f), accA1 = pk(0.0f, 0.0f);
    u64 accB0 = pk(0.0f, 0.0f), accB1 = pk(0.0f, 0.0f);

    #pragma unroll
    for (int q = 0; q < NH / 4; ++q) {
        u64 h0 = pk((float)(4 * q + 1), (float)(4 * q + 2));
        u64 h1 = pk((float)(4 * q + 3), (float)(4 * q + 4));

        u64 ampA0 = fma2(wA2, sDF[gA][2 * q],     sA0[gA][2 * q]);
        u64 ampA1 = fma2(wA2, sDF[gA][2 * q + 1], sA0[gA][2 * q + 1]);
        u64 ampB0 = fma2(wB2, sDF[gB][2 * q],     sA0[gB][2 * q]);
        u64 ampB1 = fma2(wB2, sDF[gB][2 * q + 1], sA0[gB][2 * q + 1]);

        {   u64 pr = mul2(pA2, h0);
            u64 tt = fma2(pr, IV2, MG2);
            u64 kf = sub2(tt, MG2);
            u64 r  = fma2(kf, C1n, pr);
            r      = fma2(kf, C2n, r);
            float rl, rh; upk(r, rl, rh);
            accA0  = fma2(pk(__sinf(rl), __sinf(rh)), ampA0, accA0);
        }
        {   u64 pr = mul2(pB2, h0);
            u64 tt = fma2(pr, IV2, MG2);
            u64 kf = sub2(tt, MG2);
            u64 r  = fma2(kf, C1n, pr);
            r      = fma2(kf, C2n, r);
            float rl, rh; upk(r, rl, rh);
            accB0  = fma2(pk(__sinf(rl), __sinf(rh)), ampB0, accB0);
        }
        {   u64 pr = mul2(pA2, h1);
            u64 tt = fma2(pr, IV2, MG2);
            u64 kf = sub2(tt, MG2);
            u64 r  = fma2(kf, C1n, pr);
            r      = fma2(kf, C2n, r);
            float rl, rh; upk(r, rl, rh);
            accA1  = fma2(pk(__sinf(rl), __sinf(rh)), ampA1, accA1);
        }
        {   u64 pr = mul2(pB2, h1);
            u64 tt = fma2(pr, IV2, MG2);
            u64 kf = sub2(tt, MG2);
            u64 r  = fma2(kf, C1n, pr);
            r      = fma2(kf, C2n, r);
            float rl, rh; upk(r, rl, rh);
            accB1  = fma2(pk(__sinf(rl), __sinf(rh)), ampB1, accB1);
        }
    }
    float a0l, a0h, a1l, a1h, b0l, b0h, b1l, b1h;
    upk(accA0, a0l, a0h); upk(accA1, a1l, a1h);
    upk(accB0, b0l, b0h); upk(accB1, b1l, b1h);
    out[(size_t)b * NS + nA] = (a0l + a0h) + (a1l + a1h);
    out[(size_t)b * NS + nB] = (b0l + b0h) + (b1l + b1h);
}

extern "C" void kernel_launch(void* const* d_in, const int* in_sizes, int n_in,
                              void* d_out, int out_size) {
    const float* f0   = (const float*)d_in[0];   // (8, 512)
    const float* amps = (const float*)d_in[1];   // (8, 512, 64)
    float* out = (float*)d_out;                  // (8, 262144)

    k1<<<dim3(ROWS / 256, BATCH), 256>>>(f0);
    k2<<<BATCH, 128>>>();
    k_main<<<dim3(NS / 256, BATCH), 128>>>(amps, out);
}